// round 2
// baseline (speedup 1.0000x reference)
#include <cuda_runtime.h>
#include <cuda_bf16.h>
#include <math.h>

#define NN 100000
#define DIM 128
#define HEADS 8
#define HD 16
#define EE 1600000
#define SLOPE 0.2f
#define LN_EPS 1e-5f

// ---------------- scratch (device globals; no allocation allowed) ----------------
__device__ float g_h[(size_t)NN * DIM];       // x @ W_gat
__device__ float g_asrc[NN * HEADS];
__device__ float g_adst[NN * HEADS];
__device__ unsigned g_segmax[NN * HEADS];     // order-preserving encoded float max
__device__ float g_denom[NN * HEADS];
__device__ float g_agg[(size_t)NN * DIM];     // aggregated messages
__device__ float g_h1[(size_t)NN * DIM];      // LN1 output
__device__ int g_src[EE];
__device__ int g_dst[EE];
__device__ int g_is64;

// ---------------- helpers ----------------
__device__ __forceinline__ float lrelu(float x) { return x > 0.f ? x : SLOPE * x; }

// order-preserving float -> uint map (monotonic), for atomicMax on floats incl. negatives
__device__ __forceinline__ unsigned f2o(float f) {
    unsigned u = __float_as_uint(f);
    return (u & 0x80000000u) ? ~u : (u | 0x80000000u);
}
__device__ __forceinline__ float o2f(unsigned u) {
    return (u & 0x80000000u) ? __uint_as_float(u ^ 0x80000000u) : __uint_as_float(~u);
}

// ============================================================================
// K0a: sniff edge_index dtype. int64 values < 2^31 -> every odd 32-bit word 0.
// ============================================================================
__global__ void k_detect(const unsigned* __restrict__ w) {
    unsigned nz = 0;
    for (int i = 1; i < 256; i += 2) nz |= w[i];
    g_is64 = (nz == 0) ? 1 : 0;
}

// K0b: canonicalize edge list into int32 src/dst arrays
__global__ void k_convert(const void* __restrict__ ei) {
    int i = blockIdx.x * blockDim.x + threadIdx.x;
    if (i >= 2 * EE) return;
    int v;
    if (g_is64) v = (int)((const long long*)ei)[i];
    else        v = ((const int*)ei)[i];
    if (i < EE) g_src[i] = v;
    else        g_dst[i - EE] = v;
}

// ============================================================================
// K1: h = x @ W_gat  (per 64-row tile, W resident in smem), plus
//     a_src[n,h] = <h[n,h,:], att_src[h,:]>, a_dst likewise.
// ============================================================================
__global__ void k_gat_gemm(const float* __restrict__ x,
                           const float* __restrict__ Wg,
                           const float* __restrict__ att_src,
                           const float* __restrict__ att_dst) {
    extern __shared__ float sm[];
    float* Ws = sm;                 // 128*128
    float* xs = sm + DIM * DIM;     // 64*128
    __shared__ float as_s[DIM], ad_s[DIM];

    int t = threadIdx.x;            // 256 threads
    for (int i = t; i < DIM * DIM / 4; i += 256)
        ((float4*)Ws)[i] = ((const float4*)Wg)[i];
    if (t < DIM) { as_s[t] = att_src[t]; ad_s[t] = att_dst[t]; }

    int row0 = blockIdx.x * 64;
    int nrows = min(64, NN - row0);
    for (int i = t; i < nrows * 32; i += 256) {
        int r = i >> 5, c4 = i & 31;
        ((float4*)(xs + r * DIM))[c4] = ((const float4*)(x + (size_t)(row0 + r) * DIM))[c4];
    }
    __syncthreads();

    int lane = t & 31, w = t >> 5;
    int c0 = lane * 4;
    int rbase = w * 8;
    float acc[8][4];
#pragma unroll
    for (int r = 0; r < 8; r++)
#pragma unroll
        for (int j = 0; j < 4; j++) acc[r][j] = 0.f;

#pragma unroll 4
    for (int k = 0; k < DIM; k++) {
        float4 wv = *(const float4*)(Ws + k * DIM + c0);
#pragma unroll
        for (int r = 0; r < 8; r++) {
            float xv = xs[(rbase + r) * DIM + k];
            acc[r][0] = fmaf(xv, wv.x, acc[r][0]);
            acc[r][1] = fmaf(xv, wv.y, acc[r][1]);
            acc[r][2] = fmaf(xv, wv.z, acc[r][2]);
            acc[r][3] = fmaf(xv, wv.w, acc[r][3]);
        }
    }

    int head = c0 >> 4;        // lane/4
    int cc = c0 & 15;
#pragma unroll
    for (int r = 0; r < 8; r++) {
        int row = rbase + r;
        bool live = row < nrows;
        if (live) {
            float4 hv = make_float4(acc[r][0], acc[r][1], acc[r][2], acc[r][3]);
            *(float4*)(g_h + (size_t)(row0 + row) * DIM + c0) = hv;
        }
        float ss = acc[r][0] * as_s[head * HD + cc] + acc[r][1] * as_s[head * HD + cc + 1]
                 + acc[r][2] * as_s[head * HD + cc + 2] + acc[r][3] * as_s[head * HD + cc + 3];
        float sd = acc[r][0] * ad_s[head * HD + cc] + acc[r][1] * ad_s[head * HD + cc + 1]
                 + acc[r][2] * ad_s[head * HD + cc + 2] + acc[r][3] * ad_s[head * HD + cc + 3];
        ss += __shfl_xor_sync(0xffffffffu, ss, 1);
        ss += __shfl_xor_sync(0xffffffffu, ss, 2);
        sd += __shfl_xor_sync(0xffffffffu, sd, 1);
        sd += __shfl_xor_sync(0xffffffffu, sd, 2);
        if ((lane & 3) == 0 && live) {
            g_asrc[(row0 + row) * HEADS + head] = ss;
            g_adst[(row0 + row) * HEADS + head] = sd;
        }
    }
}

// ============================================================================
// K2: self-loop initializes segmax (plain store)
// ============================================================================
__global__ void k_self_max() {
    int idx = blockIdx.x * blockDim.x + threadIdx.x;
    if (idx >= NN * HEADS) return;
    float e = lrelu(g_asrc[idx] + g_adst[idx]);
    g_segmax[idx] = f2o(e);
}

// K3: per-(edge,head) atomicMax into dst segments
__global__ void k_edge_max() {
    int idx = blockIdx.x * blockDim.x + threadIdx.x;
    if (idx >= EE * HEADS) return;
    int e = idx >> 3, hh = idx & 7;
    int s = g_src[e];
    int d = g_dst[e];
    float v = lrelu(g_asrc[s * HEADS + hh] + g_adst[d * HEADS + hh]);
    atomicMax(&g_segmax[d * HEADS + hh], f2o(v));
}

// K4: self-loop initializes denom (plain store)
__global__ void k_self_denom() {
    int idx = blockIdx.x * blockDim.x + threadIdx.x;
    if (idx >= NN * HEADS) return;
    float e = lrelu(g_asrc[idx] + g_adst[idx]);
    g_denom[idx] = expf(e - o2f(g_segmax[idx]));
}

// K5: per-(edge,head) denom accumulation
__global__ void k_edge_denom() {
    int idx = blockIdx.x * blockDim.x + threadIdx.x;
    if (idx >= EE * HEADS) return;
    int e = idx >> 3, hh = idx & 7;
    int s = g_src[e];
    int d = g_dst[e];
    float v = lrelu(g_asrc[s * HEADS + hh] + g_adst[d * HEADS + hh]);
    atomicAdd(&g_denom[d * HEADS + hh], expf(v - o2f(g_segmax[d * HEADS + hh])));
}

// K6: self-loop initializes agg (plain store): agg[n,:] = h[n,:]*alpha_self
__global__ void k_self_agg() {
    int idx = blockIdx.x * blockDim.x + threadIdx.x;
    if (idx >= NN * DIM) return;
    int n = idx >> 7, c = idx & 127;
    int hh = c >> 4;
    int nh = n * HEADS + hh;
    float e = lrelu(g_asrc[nh] + g_adst[nh]);
    float alpha = expf(e - o2f(g_segmax[nh])) / (g_denom[nh] + 1e-16f);
    g_agg[idx] = g_h[idx] * alpha;
}

// K7: one warp per edge: agg[dst,:] += h[src,:]*alpha
__global__ void k_edge_agg() {
    int gw = (blockIdx.x * blockDim.x + threadIdx.x) >> 5;
    if (gw >= EE) return;
    int lane = threadIdx.x & 31;
    int s = g_src[gw];
    int d = g_dst[gw];
    int hh = lane >> 2;                 // head for this lane's 4 channels
    int nh = d * HEADS + hh;
    float v = lrelu(g_asrc[s * HEADS + hh] + g_adst[nh]);
    float alpha = expf(v - o2f(g_segmax[nh])) / (g_denom[nh] + 1e-16f);
    int c0 = lane * 4;
    float4 hv = *(const float4*)(g_h + (size_t)s * DIM + c0);
    float* ap = g_agg + (size_t)d * DIM + c0;
    atomicAdd(ap + 0, hv.x * alpha);
    atomicAdd(ap + 1, hv.y * alpha);
    atomicAdd(ap + 2, hv.z * alpha);
    atomicAdd(ap + 3, hv.w * alpha);
}

// ============================================================================
// K8: h1 = LayerNorm(x + agg + b_gat) ; one warp per row
// ============================================================================
__global__ void k_ln1(const float* __restrict__ x,
                      const float* __restrict__ b_gat,
                      const float* __restrict__ gamma,
                      const float* __restrict__ beta) {
    int row = (blockIdx.x * blockDim.x + threadIdx.x) >> 5;
    if (row >= NN) return;
    int lane = threadIdx.x & 31;
    int c0 = lane * 4;
    float4 xv = *(const float4*)(x + (size_t)row * DIM + c0);
    float4 av = *(const float4*)(g_agg + (size_t)row * DIM + c0);
    float4 bv = *(const float4*)(b_gat + c0);
    float v[4] = {xv.x + av.x + bv.x, xv.y + av.y + bv.y,
                  xv.z + av.z + bv.z, xv.w + av.w + bv.w};
    float sum = v[0] + v[1] + v[2] + v[3];
#pragma unroll
    for (int o = 16; o > 0; o >>= 1) sum += __shfl_xor_sync(0xffffffffu, sum, o);
    float mu = sum * (1.f / DIM);
    float sq = 0.f;
#pragma unroll
    for (int j = 0; j < 4; j++) { float dd = v[j] - mu; sq += dd * dd; }
#pragma unroll
    for (int o = 16; o > 0; o >>= 1) sq += __shfl_xor_sync(0xffffffffu, sq, o);
    float rs = rsqrtf(sq * (1.f / DIM) + LN_EPS);
    float4 gv = *(const float4*)(gamma + c0);
    float4 be = *(const float4*)(beta + c0);
    float4 out;
    out.x = gv.x * (v[0] - mu) * rs + be.x;
    out.y = gv.y * (v[1] - mu) * rs + be.y;
    out.z = gv.z * (v[2] - mu) * rs + be.z;
    out.w = gv.w * (v[3] - mu) * rs + be.w;
    *(float4*)(g_h1 + (size_t)row * DIM + c0) = out;
}

// ============================================================================
// K9: fused FFN + residual + LN2:
//   out = LN(h1 + gelu(h1@W1+b1)@W2 + b2)
// 64-row tiles; [64,512] intermediate staged through smem per 128-col k-tile.
// ============================================================================
__global__ void k_ffn(const float* __restrict__ W1,
                      const float* __restrict__ b1,
                      const float* __restrict__ W2,
                      const float* __restrict__ b2,
                      const float* __restrict__ gamma,
                      const float* __restrict__ beta,
                      float* __restrict__ out) {
    extern __shared__ float sm[];
    float* h1s  = sm;                       // 64*128
    float* ws   = sm + 64 * DIM;            // 128*128
    float* mids = ws + DIM * DIM;           // 64*128

    int t = threadIdx.x;  // 256
    int row0 = blockIdx.x * 64;
    int nrows = min(64, NN - row0);
    for (int i = t; i < nrows * 32; i += 256) {
        int r = i >> 5, c4 = i & 31;
        ((float4*)(h1s + r * DIM))[c4] = ((const float4*)(g_h1 + (size_t)(row0 + r) * DIM))[c4];
    }

    int lane = t & 31, w = t >> 5;
    int c0 = lane * 4;
    int rbase = w * 8;
    float acc[8][4];
#pragma unroll
    for (int r = 0; r < 8; r++)
#pragma unroll
        for (int j = 0; j < 4; j++) acc[r][j] = 0.f;

    for (int kt = 0; kt < 4; kt++) {
        __syncthreads();   // done with previous ws use
        // load W1 tile [128 x 128]: rows k, cols kt*128..
        for (int i = t; i < DIM * 32; i += 256) {
            int k = i >> 5, c4 = i & 31;
            ((float4*)(ws + k * DIM))[c4] =
                ((const float4*)(W1 + (size_t)k * 512 + kt * DIM))[c4];
        }
        __syncthreads();

        float m[8][4];
        float4 b1v = *(const float4*)(b1 + kt * DIM + c0);
#pragma unroll
        for (int r = 0; r < 8; r++) { m[r][0] = b1v.x; m[r][1] = b1v.y; m[r][2] = b1v.z; m[r][3] = b1v.w; }
#pragma unroll 4
        for (int k = 0; k < DIM; k++) {
            float4 wv = *(const float4*)(ws + k * DIM + c0);
#pragma unroll
            for (int r = 0; r < 8; r++) {
                float xv = h1s[(rbase + r) * DIM + k];
                m[r][0] = fmaf(xv, wv.x, m[r][0]);
                m[r][1] = fmaf(xv, wv.y, m[r][1]);
                m[r][2] = fmaf(xv, wv.z, m[r][2]);
                m[r][3] = fmaf(xv, wv.w, m[r][3]);
            }
        }
        // exact GELU, write to mids
#pragma unroll
        for (int r = 0; r < 8; r++) {
#pragma unroll
            for (int j = 0; j < 4; j++)
                m[r][j] = 0.5f * m[r][j] * (1.f + erff(m[r][j] * 0.70710678118654752f));
            *(float4*)(mids + (rbase + r) * DIM + c0) = make_float4(m[r][0], m[r][1], m[r][2], m[r][3]);
        }
        __syncthreads();   // mids ready, ws free
        // load W2 tile [128 x 128]: rows kt*128.., all 128 cols (contiguous)
        for (int i = t; i < DIM * 32; i += 256)
            ((float4*)ws)[i] = ((const float4*)(W2 + (size_t)kt * DIM * DIM))[i];
        __syncthreads();
#pragma unroll 4
        for (int k = 0; k < DIM; k++) {
            float4 wv = *(const float4*)(ws + k * DIM + c0);
#pragma unroll
            for (int r = 0; r < 8; r++) {
                float xv = mids[(rbase + r) * DIM + k];
                acc[r][0] = fmaf(xv, wv.x, acc[r][0]);
                acc[r][1] = fmaf(xv, wv.y, acc[r][1]);
                acc[r][2] = fmaf(xv, wv.z, acc[r][2]);
                acc[r][3] = fmaf(xv, wv.w, acc[r][3]);
            }
        }
    }

    // residual + LN2; each warp holds full rows rbase..rbase+7 across lanes
    float4 b2v = *(const float4*)(b2 + c0);
    float4 gv = *(const float4*)(gamma + c0);
    float4 be = *(const float4*)(beta + c0);
#pragma unroll
    for (int r = 0; r < 8; r++) {
        float v[4];
        v[0] = acc[r][0] + b2v.x + h1s[(rbase + r) * DIM + c0 + 0];
        v[1] = acc[r][1] + b2v.y + h1s[(rbase + r) * DIM + c0 + 1];
        v[2] = acc[r][2] + b2v.z + h1s[(rbase + r) * DIM + c0 + 2];
        v[3] = acc[r][3] + b2v.w + h1s[(rbase + r) * DIM + c0 + 3];
        float sum = v[0] + v[1] + v[2] + v[3];
#pragma unroll
        for (int o = 16; o > 0; o >>= 1) sum += __shfl_xor_sync(0xffffffffu, sum, o);
        float mu = sum * (1.f / DIM);
        float sq = 0.f;
#pragma unroll
        for (int j = 0; j < 4; j++) { float dd = v[j] - mu; sq += dd * dd; }
#pragma unroll
        for (int o = 16; o > 0; o >>= 1) sq += __shfl_xor_sync(0xffffffffu, sq, o);
        float rs = rsqrtf(sq * (1.f / DIM) + LN_EPS);
        int row = rbase + r;
        if (row < nrows) {
            float4 o4;
            o4.x = gv.x * (v[0] - mu) * rs + be.x;
            o4.y = gv.y * (v[1] - mu) * rs + be.y;
            o4.z = gv.z * (v[2] - mu) * rs + be.z;
            o4.w = gv.w * (v[3] - mu) * rs + be.w;
            *(float4*)(out + (size_t)(row0 + row) * DIM + c0) = o4;
        }
    }
}

// ============================================================================
extern "C" void kernel_launch(void* const* d_in, const int* in_sizes, int n_in,
                              void* d_out, int out_size) {
    const float* x        = (const float*)d_in[0];
    const void*  ei       = d_in[1];
    const float* W_gat    = (const float*)d_in[2];
    const float* att_src  = (const float*)d_in[3];
    const float* att_dst  = (const float*)d_in[4];
    const float* b_gat    = (const float*)d_in[5];
    const float* gamma    = (const float*)d_in[6];
    const float* beta     = (const float*)d_in[7];
    const float* W1       = (const float*)d_in[8];
    const float* b1       = (const float*)d_in[9];
    const float* W2       = (const float*)d_in[10];
    const float* b2       = (const float*)d_in[11];
    float* out = (float*)d_out;

    const int smem_gat = (DIM * DIM + 64 * DIM) * sizeof(float);       // 96 KB
    const int smem_ffn = (64 * DIM + DIM * DIM + 64 * DIM) * sizeof(float); // 128 KB
    cudaFuncSetAttribute(k_gat_gemm, cudaFuncAttributeMaxDynamicSharedMemorySize, smem_gat);
    cudaFuncSetAttribute(k_ffn, cudaFuncAttributeMaxDynamicSharedMemorySize, smem_ffn);

    const int rowBlocks = (NN + 63) / 64;   // 1563

    k_detect<<<1, 1>>>((const unsigned*)ei);
    k_convert<<<(2 * EE + 255) / 256, 256>>>(ei);
    k_gat_gemm<<<rowBlocks, 256, smem_gat>>>(x, W_gat, att_src, att_dst);
    k_self_max<<<(NN * HEADS + 255) / 256, 256>>>();
    k_edge_max<<<(EE * HEADS + 255) / 256, 256>>>();
    k_self_denom<<<(NN * HEADS + 255) / 256, 256>>>();
    k_edge_denom<<<(EE * HEADS + 255) / 256, 256>>>();
    k_self_agg<<<(NN * DIM + 255) / 256, 256>>>();
    k_edge_agg<<<(EE + 7) / 8, 256>>>();          // 1 warp/edge, 8 warps/block
    k_ln1<<<(NN + 7) / 8, 256>>>(x, b_gat, gamma, beta);
    k_ffn<<<rowBlocks, 256, smem_ffn>>>(W1, b1, W2, b2, gamma, beta, out);
}

// round 3
// speedup vs baseline: 1.3230x; 1.3230x over previous
#include <cuda_runtime.h>
#include <cuda_bf16.h>
#include <math.h>

#define NN 100000
#define DIM 128
#define HEADS 8
#define HD 16
#define EE 1600000
#define SLOPE 0.2f
#define LN_EPS 1e-5f

// ---------------- scratch (device globals; no allocation allowed) ----------------
__device__ float g_h[(size_t)NN * DIM];       // x @ W_gat
__device__ float g_asrc[NN * HEADS];
__device__ float g_adst[NN * HEADS];
__device__ float g_denom[NN * HEADS];         // sum of exp(e) per (node, head)
__device__ float g_agg[(size_t)NN * DIM];     // UNnormalized aggregated messages
__device__ int g_src[EE];
__device__ int g_dst[EE];
__device__ int g_is64;

// ---------------- helpers ----------------
__device__ __forceinline__ float lrelu(float x) { return x > 0.f ? x : SLOPE * x; }

// packed f32x2 helpers (sm_103a)
__device__ __forceinline__ unsigned long long dup2(float x) {
    unsigned long long r; unsigned u = __float_as_uint(x);
    asm("mov.b64 %0, {%1, %2};" : "=l"(r) : "r"(u), "r"(u));
    return r;
}
__device__ __forceinline__ unsigned long long fma2(unsigned long long a, unsigned long long b, unsigned long long c) {
    unsigned long long d;
    asm("fma.rn.f32x2 %0, %1, %2, %3;" : "=l"(d) : "l"(a), "l"(b), "l"(c));
    return d;
}
__device__ __forceinline__ float2 unpk(unsigned long long v) {
    unsigned lo, hi;
    asm("mov.b64 {%0, %1}, %2;" : "=r"(lo), "=r"(hi) : "l"(v));
    return make_float2(__uint_as_float(lo), __uint_as_float(hi));
}

// ============================================================================
// K0a: sniff edge_index dtype. int64 values < 2^31 -> every odd 32-bit word 0.
// ============================================================================
__global__ void k_detect(const unsigned* __restrict__ w) {
    unsigned nz = 0;
    for (int i = 1; i < 256; i += 2) nz |= w[i];
    g_is64 = (nz == 0) ? 1 : 0;
}

// K0b: canonicalize edge list into int32 src/dst arrays
__global__ void k_convert(const void* __restrict__ ei) {
    int i = blockIdx.x * blockDim.x + threadIdx.x;
    if (i >= 2 * EE) return;
    int v;
    if (g_is64) v = (int)((const long long*)ei)[i];
    else        v = ((const int*)ei)[i];
    if (i < EE) g_src[i] = v;
    else        g_dst[i - EE] = v;
}

// ============================================================================
// K1: h = x @ W_gat (packed f32x2 FMA), plus attention dots a_src/a_dst.
// 64-row tiles, 8 warps; each thread: 8 rows x 4 cols.
// ============================================================================
__global__ void __launch_bounds__(256, 1)
k_gat_gemm(const float* __restrict__ x,
           const float* __restrict__ Wg,
           const float* __restrict__ att_src,
           const float* __restrict__ att_dst) {
    extern __shared__ float sm[];
    float* Ws = sm;                 // 128*128
    float* xs = sm + DIM * DIM;     // 64*128
    __shared__ float as_s[DIM], ad_s[DIM];

    int t = threadIdx.x;            // 256 threads
    for (int i = t; i < DIM * DIM / 4; i += 256)
        ((float4*)Ws)[i] = ((const float4*)Wg)[i];
    if (t < DIM) { as_s[t] = att_src[t]; ad_s[t] = att_dst[t]; }

    int row0 = blockIdx.x * 64;
    int nrows = min(64, NN - row0);
    for (int i = t; i < nrows * 32; i += 256) {
        int r = i >> 5, c4 = i & 31;
        ((float4*)(xs + r * DIM))[c4] = ((const float4*)(x + (size_t)(row0 + r) * DIM))[c4];
    }
    __syncthreads();

    int lane = t & 31, w = t >> 5;
    int c0 = lane * 4;
    int rbase = w * 8;
    unsigned long long acc2[8][2];
#pragma unroll
    for (int r = 0; r < 8; r++) { acc2[r][0] = 0ull; acc2[r][1] = 0ull; }

    for (int k4 = 0; k4 < DIM; k4 += 4) {
        float4 xr[8];
#pragma unroll
        for (int r = 0; r < 8; r++)
            xr[r] = *(const float4*)(xs + (rbase + r) * DIM + k4);
#pragma unroll
        for (int kk = 0; kk < 4; kk++) {
            ulonglong2 wv = *(const ulonglong2*)(Ws + (k4 + kk) * DIM + c0);
#pragma unroll
            for (int r = 0; r < 8; r++) {
                float xv = (kk == 0) ? xr[r].x : (kk == 1) ? xr[r].y : (kk == 2) ? xr[r].z : xr[r].w;
                unsigned long long xd = dup2(xv);
                acc2[r][0] = fma2(xd, wv.x, acc2[r][0]);
                acc2[r][1] = fma2(xd, wv.y, acc2[r][1]);
            }
        }
    }

    int head = c0 >> 4;        // lane/4
    int cc = c0 & 15;
#pragma unroll
    for (int r = 0; r < 8; r++) {
        int row = rbase + r;
        bool live = row < nrows;
        float2 p0 = unpk(acc2[r][0]);
        float2 p1 = unpk(acc2[r][1]);
        float a0 = p0.x, a1 = p0.y, a2 = p1.x, a3 = p1.y;
        if (live)
            *(float4*)(g_h + (size_t)(row0 + row) * DIM + c0) = make_float4(a0, a1, a2, a3);
        float ss = a0 * as_s[head * HD + cc] + a1 * as_s[head * HD + cc + 1]
                 + a2 * as_s[head * HD + cc + 2] + a3 * as_s[head * HD + cc + 3];
        float sd = a0 * ad_s[head * HD + cc] + a1 * ad_s[head * HD + cc + 1]
                 + a2 * ad_s[head * HD + cc + 2] + a3 * ad_s[head * HD + cc + 3];
        ss += __shfl_xor_sync(0xffffffffu, ss, 1);
        ss += __shfl_xor_sync(0xffffffffu, ss, 2);
        sd += __shfl_xor_sync(0xffffffffu, sd, 1);
        sd += __shfl_xor_sync(0xffffffffu, sd, 2);
        if ((lane & 3) == 0 && live) {
            g_asrc[(row0 + row) * HEADS + head] = ss;
            g_adst[(row0 + row) * HEADS + head] = sd;
        }
    }
}

// ============================================================================
// K2: self-loop initializes agg (unnormalized) and denom with plain stores.
//     agg[n,:] = exp(e_self)*h[n,:] ; denom[n,h] = exp(e_self)
// ============================================================================
__global__ void k_self() {
    int idx = blockIdx.x * blockDim.x + threadIdx.x;   // over NN*32 float4s
    if (idx >= NN * 32) return;
    int n = idx >> 5, c4 = idx & 31;
    int hh = c4 >> 2;
    int nh = n * HEADS + hh;
    float e = lrelu(g_asrc[nh] + g_adst[nh]);
    float wgt = expf(e);
    float4 hv = ((const float4*)(g_h + (size_t)n * DIM))[c4];
    float4 o = make_float4(hv.x * wgt, hv.y * wgt, hv.z * wgt, hv.w * wgt);
    ((float4*)(g_agg + (size_t)n * DIM))[c4] = o;
    if ((c4 & 3) == 0) g_denom[nh] = wgt;
}

// ============================================================================
// K3: ONE edge sweep: denom += exp(e); agg[dst,:] += exp(e)*h[src,:]
//     one warp per edge; vector red.v4 for the message.
// ============================================================================
__global__ void k_edge() {
    int gw = (blockIdx.x * blockDim.x + threadIdx.x) >> 5;
    if (gw >= EE) return;
    int lane = threadIdx.x & 31;
    int s = g_src[gw];
    int d = g_dst[gw];
    int hh = lane >> 2;                 // head for this lane's 4 channels
    float e = lrelu(g_asrc[s * HEADS + hh] + g_adst[d * HEADS + hh]);
    float wgt = expf(e);
    if ((lane & 3) == 0) atomicAdd(&g_denom[d * HEADS + hh], wgt);
    int c0 = lane * 4;
    float4 hv = *(const float4*)(g_h + (size_t)s * DIM + c0);
    float* ap = g_agg + (size_t)d * DIM + c0;
    asm volatile("red.global.add.v4.f32 [%0], {%1, %2, %3, %4};"
                 :: "l"(ap), "f"(hv.x * wgt), "f"(hv.y * wgt), "f"(hv.z * wgt), "f"(hv.w * wgt)
                 : "memory");
}

// ============================================================================
// K4: fused LN1 + FFN + residual + LN2:
//   h1 = LN(x + agg/denom + b_gat);  out = LN(h1 + gelu(h1@W1+b1)@W2 + b2)
// 64-row tiles; packed f32x2 FMAs; W1/W2 tiles double-buffered in smem.
// ============================================================================
__global__ void __launch_bounds__(256, 1)
k_ffn(const float* __restrict__ x,
      const float* __restrict__ b_gat,
      const float* __restrict__ W1,
      const float* __restrict__ b1,
      const float* __restrict__ W2,
      const float* __restrict__ b2,
      const float* __restrict__ gamma,
      const float* __restrict__ beta,
      float* __restrict__ out) {
    extern __shared__ float sm[];
    float* h1s  = sm;                        // 64*128   (32 KB)
    float* ws1  = sm + 64 * DIM;             // 128*128  (64 KB)
    float* ws2  = ws1 + DIM * DIM;           // 128*128  (64 KB)
    float* mids = ws2 + DIM * DIM;           // 64*128   (32 KB)

    int t = threadIdx.x;  // 256
    int lane = t & 31, w = t >> 5;
    int c0 = lane * 4;
    int rbase = w * 8;
    int head = c0 >> 4;
    int row0 = blockIdx.x * 64;
    int nrows = min(64, NN - row0);

    float4 gv = *(const float4*)(gamma + c0);
    float4 be = *(const float4*)(beta + c0);

    // ---- fused LN1: each warp normalizes its own 8 rows into h1s ----
    {
        float4 bg = *(const float4*)(b_gat + c0);
#pragma unroll
        for (int r = 0; r < 8; r++) {
            int row = rbase + r;
            if (row < nrows) {
                size_t off = (size_t)(row0 + row) * DIM + c0;
                float4 xv = *(const float4*)(x + off);
                float4 av = *(const float4*)(g_agg + off);
                float rd = 1.f / (g_denom[(row0 + row) * HEADS + head] + 1e-16f);
                float v[4] = {xv.x + av.x * rd + bg.x, xv.y + av.y * rd + bg.y,
                              xv.z + av.z * rd + bg.z, xv.w + av.w * rd + bg.w};
                float sum = v[0] + v[1] + v[2] + v[3];
#pragma unroll
                for (int o = 16; o > 0; o >>= 1) sum += __shfl_xor_sync(0xffffffffu, sum, o);
                float mu = sum * (1.f / DIM);
                float sq = 0.f;
#pragma unroll
                for (int j = 0; j < 4; j++) { float dd = v[j] - mu; sq += dd * dd; }
#pragma unroll
                for (int o = 16; o > 0; o >>= 1) sq += __shfl_xor_sync(0xffffffffu, sq, o);
                float rs = rsqrtf(sq * (1.f / DIM) + LN_EPS);
                float4 o4;
                o4.x = gv.x * (v[0] - mu) * rs + be.x;
                o4.y = gv.y * (v[1] - mu) * rs + be.y;
                o4.z = gv.z * (v[2] - mu) * rs + be.z;
                o4.w = gv.w * (v[3] - mu) * rs + be.w;
                *(float4*)(h1s + row * DIM + c0) = o4;
            } else {
                *(float4*)(h1s + row * DIM + c0) = make_float4(0.f, 0.f, 0.f, 0.f);
            }
        }
    }

    unsigned long long acc2[8][2];
#pragma unroll
    for (int r = 0; r < 8; r++) { acc2[r][0] = 0ull; acc2[r][1] = 0ull; }

    for (int kt = 0; kt < 4; kt++) {
        __syncthreads();   // previous ws use done (also orders h1s on kt=0)
        // load W1 tile [k=0..127][cols kt*128..] and W2 tile [rows kt*128..][all cols]
        for (int i = t; i < DIM * 32; i += 256) {
            int k = i >> 5, c4 = i & 31;
            ((float4*)(ws1 + k * DIM))[c4] =
                ((const float4*)(W1 + (size_t)k * 512 + kt * DIM))[c4];
        }
        for (int i = t; i < DIM * 32; i += 256)
            ((float4*)ws2)[i] = ((const float4*)(W2 + (size_t)kt * DIM * DIM))[i];
        __syncthreads();

        // ---- GEMM1 tile: mid = h1 @ W1_tile + b1_tile ----
        unsigned long long m2[8][2];
        {
            float4 b1v = *(const float4*)(b1 + kt * DIM + c0);
            unsigned long long blo, bhi;
            asm("mov.b64 %0, {%1, %2};" : "=l"(blo) : "r"(__float_as_uint(b1v.x)), "r"(__float_as_uint(b1v.y)));
            asm("mov.b64 %0, {%1, %2};" : "=l"(bhi) : "r"(__float_as_uint(b1v.z)), "r"(__float_as_uint(b1v.w)));
#pragma unroll
            for (int r = 0; r < 8; r++) { m2[r][0] = blo; m2[r][1] = bhi; }
        }
        for (int k4 = 0; k4 < DIM; k4 += 4) {
            float4 xr[8];
#pragma unroll
            for (int r = 0; r < 8; r++)
                xr[r] = *(const float4*)(h1s + (rbase + r) * DIM + k4);
#pragma unroll
            for (int kk = 0; kk < 4; kk++) {
                ulonglong2 wv = *(const ulonglong2*)(ws1 + (k4 + kk) * DIM + c0);
#pragma unroll
                for (int r = 0; r < 8; r++) {
                    float xv = (kk == 0) ? xr[r].x : (kk == 1) ? xr[r].y : (kk == 2) ? xr[r].z : xr[r].w;
                    unsigned long long xd = dup2(xv);
                    m2[r][0] = fma2(xd, wv.x, m2[r][0]);
                    m2[r][1] = fma2(xd, wv.y, m2[r][1]);
                }
            }
        }
        // exact GELU -> mids (warp-private rows; warp-level sync suffices)
#pragma unroll
        for (int r = 0; r < 8; r++) {
            float2 p0 = unpk(m2[r][0]);
            float2 p1 = unpk(m2[r][1]);
            float mm[4] = {p0.x, p0.y, p1.x, p1.y};
#pragma unroll
            for (int j = 0; j < 4; j++)
                mm[j] = 0.5f * mm[j] * (1.f + erff(mm[j] * 0.70710678118654752f));
            *(float4*)(mids + (rbase + r) * DIM + c0) = make_float4(mm[0], mm[1], mm[2], mm[3]);
        }
        __syncwarp();

        // ---- GEMM2 tile: acc += gelu(mid) @ W2_tile ----
        for (int k4 = 0; k4 < DIM; k4 += 4) {
            float4 xr[8];
#pragma unroll
            for (int r = 0; r < 8; r++)
                xr[r] = *(const float4*)(mids + (rbase + r) * DIM + k4);
#pragma unroll
            for (int kk = 0; kk < 4; kk++) {
                ulonglong2 wv = *(const ulonglong2*)(ws2 + (k4 + kk) * DIM + c0);
#pragma unroll
                for (int r = 0; r < 8; r++) {
                    float xv = (kk == 0) ? xr[r].x : (kk == 1) ? xr[r].y : (kk == 2) ? xr[r].z : xr[r].w;
                    unsigned long long xd = dup2(xv);
                    acc2[r][0] = fma2(xd, wv.x, acc2[r][0]);
                    acc2[r][1] = fma2(xd, wv.y, acc2[r][1]);
                }
            }
        }
        __syncwarp();   // mids reuse next kt guarded by the block sync at loop top
    }

    // ---- residual + LN2 ----
    float4 b2v = *(const float4*)(b2 + c0);
#pragma unroll
    for (int r = 0; r < 8; r++) {
        int row = rbase + r;
        if (row >= nrows) continue;
        float2 p0 = unpk(acc2[r][0]);
        float2 p1 = unpk(acc2[r][1]);
        float v[4];
        v[0] = p0.x + b2v.x + h1s[row * DIM + c0 + 0];
        v[1] = p0.y + b2v.y + h1s[row * DIM + c0 + 1];
        v[2] = p1.x + b2v.z + h1s[row * DIM + c0 + 2];
        v[3] = p1.y + b2v.w + h1s[row * DIM + c0 + 3];
        float sum = v[0] + v[1] + v[2] + v[3];
#pragma unroll
        for (int o = 16; o > 0; o >>= 1) sum += __shfl_xor_sync(0xffffffffu, sum, o);
        float mu = sum * (1.f / DIM);
        float sq = 0.f;
#pragma unroll
        for (int j = 0; j < 4; j++) { float dd = v[j] - mu; sq += dd * dd; }
#pragma unroll
        for (int o = 16; o > 0; o >>= 1) sq += __shfl_xor_sync(0xffffffffu, sq, o);
        float rs = rsqrtf(sq * (1.f / DIM) + LN_EPS);
        float4 o4;
        o4.x = gv.x * (v[0] - mu) * rs + be.x;
        o4.y = gv.y * (v[1] - mu) * rs + be.y;
        o4.z = gv.z * (v[2] - mu) * rs + be.z;
        o4.w = gv.w * (v[3] - mu) * rs + be.w;
        *(float4*)(out + (size_t)(row0 + row) * DIM + c0) = o4;
    }
}

// ============================================================================
extern "C" void kernel_launch(void* const* d_in, const int* in_sizes, int n_in,
                              void* d_out, int out_size) {
    const float* x        = (const float*)d_in[0];
    const void*  ei       = d_in[1];
    const float* W_gat    = (const float*)d_in[2];
    const float* att_src  = (const float*)d_in[3];
    const float* att_dst  = (const float*)d_in[4];
    const float* b_gat    = (const float*)d_in[5];
    const float* gamma    = (const float*)d_in[6];
    const float* beta     = (const float*)d_in[7];
    const float* W1       = (const float*)d_in[8];
    const float* b1       = (const float*)d_in[9];
    const float* W2       = (const float*)d_in[10];
    const float* b2       = (const float*)d_in[11];
    float* out = (float*)d_out;

    const int smem_gat = (DIM * DIM + 64 * DIM) * sizeof(float);            // 96 KB
    const int smem_ffn = (64 * DIM + 2 * DIM * DIM + 64 * DIM) * sizeof(float); // 192 KB
    cudaFuncSetAttribute(k_gat_gemm, cudaFuncAttributeMaxDynamicSharedMemorySize, smem_gat);
    cudaFuncSetAttribute(k_ffn, cudaFuncAttributeMaxDynamicSharedMemorySize, smem_ffn);

    const int rowBlocks = (NN + 63) / 64;   // 1563

    k_detect<<<1, 1>>>((const unsigned*)ei);
    k_convert<<<(2 * EE + 255) / 256, 256>>>(ei);
    k_gat_gemm<<<rowBlocks, 256, smem_gat>>>(x, W_gat, att_src, att_dst);
    k_self<<<(NN * 32 + 255) / 256, 256>>>();
    k_edge<<<(EE + 7) / 8, 256>>>();        // 1 warp/edge, 8 warps/block
    k_ffn<<<rowBlocks, 256, smem_ffn>>>(x, b_gat, W1, b1, W2, b2, gamma, beta, out);
}

// round 5
// speedup vs baseline: 1.4180x; 1.0718x over previous
#include <cuda_runtime.h>
#include <cuda_bf16.h>
#include <math.h>

#define NN 100000
#define DIM 128
#define HEADS 8
#define HD 16
#define EE 1600000
#define SLOPE 0.2f
#define LN_EPS 1e-5f

// ---------------- scratch (device globals; no allocation allowed) ----------------
__device__ float g_h[(size_t)NN * DIM];       // x @ W_gat
__device__ float g_asrc[NN * HEADS];
__device__ float g_adst[NN * HEADS];
__device__ float g_denom[NN * HEADS];         // sum of exp(e) per (node, head)
__device__ float g_agg[(size_t)NN * DIM];     // UNnormalized aggregated messages
__device__ int g_src[EE];
__device__ int g_dst[EE];
__device__ int g_deg[NN];
__device__ int g_start[NN + 1];
__device__ int g_cursor[NN];
__device__ int g_csr[EE];                      // src ids grouped by dst
__device__ int g_is64;

// ---------------- helpers ----------------
__device__ __forceinline__ float lrelu(float x) { return x > 0.f ? x : SLOPE * x; }

// packed f32x2 helpers (sm_103a)
__device__ __forceinline__ unsigned long long dup2(float x) {
    unsigned long long r; unsigned u = __float_as_uint(x);
    asm("mov.b64 %0, {%1, %2};" : "=l"(r) : "r"(u), "r"(u));
    return r;
}
__device__ __forceinline__ unsigned long long fma2(unsigned long long a, unsigned long long b, unsigned long long c) {
    unsigned long long d;
    asm("fma.rn.f32x2 %0, %1, %2, %3;" : "=l"(d) : "l"(a), "l"(b), "l"(c));
    return d;
}
__device__ __forceinline__ float2 unpk(unsigned long long v) {
    unsigned lo, hi;
    asm("mov.b64 {%0, %1}, %2;" : "=r"(lo), "=r"(hi) : "l"(v));
    return make_float2(__uint_as_float(lo), __uint_as_float(hi));
}

// ============================================================================
// K0a: sniff edge_index dtype. int64 values < 2^31 -> every odd 32-bit word 0.
// ============================================================================
__global__ void k_detect(const unsigned* __restrict__ w) {
    unsigned nz = 0;
    for (int i = 1; i < 256; i += 2) nz |= w[i];
    g_is64 = (nz == 0) ? 1 : 0;
}

// K0b: canonicalize edge list into int32 src/dst arrays; zero degree histogram
__global__ void k_convert(const void* __restrict__ ei) {
    int i = blockIdx.x * blockDim.x + threadIdx.x;
    if (i >= 2 * EE) return;
    int v;
    if (g_is64) v = (int)((const long long*)ei)[i];
    else        v = ((const int*)ei)[i];
    if (i < EE) g_src[i] = v;
    else        g_dst[i - EE] = v;
    if (i < NN) g_deg[i] = 0;
}

// K0c: degree histogram over destinations
__global__ void k_hist() {
    int i = blockIdx.x * blockDim.x + threadIdx.x;
    if (i >= EE) return;
    atomicAdd(&g_deg[g_dst[i]], 1);
}

// K0d: single-block exclusive scan of degrees -> g_start, g_cursor
__global__ void __launch_bounds__(1024, 1) k_scan() {
    __shared__ int warp_tot[32];
    __shared__ int s_tot;
    int t = threadIdx.x, lane = t & 31, wid = t >> 5;
    int carry = 0;
    for (int base = 0; base < NN; base += 1024) {
        int i = base + t;
        int v = (i < NN) ? g_deg[i] : 0;
        int incl = v;
#pragma unroll
        for (int o = 1; o < 32; o <<= 1) {
            int n = __shfl_up_sync(0xffffffffu, incl, o);
            if (lane >= o) incl += n;
        }
        if (lane == 31) warp_tot[wid] = incl;
        __syncthreads();
        if (wid == 0) {
            int wv = warp_tot[lane];
            int wincl = wv;
#pragma unroll
            for (int o = 1; o < 32; o <<= 1) {
                int n = __shfl_up_sync(0xffffffffu, wincl, o);
                if (lane >= o) wincl += n;
            }
            warp_tot[lane] = wincl - wv;   // exclusive warp offsets
        }
        __syncthreads();
        int excl = carry + warp_tot[wid] + (incl - v);
        if (i < NN) { g_start[i] = excl; g_cursor[i] = excl; }
        if (t == 1023) s_tot = excl + v;
        __syncthreads();
        carry = s_tot;
    }
    if (t == 0) g_start[NN] = carry;
}

// K0e: scatter src ids into dst buckets
__global__ void k_scatter() {
    int i = blockIdx.x * blockDim.x + threadIdx.x;
    if (i >= EE) return;
    int d = g_dst[i];
    int pos = atomicAdd(&g_cursor[d], 1);
    g_csr[pos] = g_src[i];
}

// ============================================================================
// K1: h = x @ W_gat (packed f32x2 FMA), attention dots, AND self-loop init of
//     g_agg / g_denom (acc values still in registers).
// ============================================================================
__global__ void __launch_bounds__(256, 1)
k_gat_gemm(const float* __restrict__ x,
           const float* __restrict__ Wg,
           const float* __restrict__ att_src,
           const float* __restrict__ att_dst) {
    extern __shared__ float sm[];
    float* Ws = sm;                 // 128*128
    float* xs = sm + DIM * DIM;     // 64*128
    __shared__ float as_s[DIM], ad_s[DIM];

    int t = threadIdx.x;            // 256 threads
    for (int i = t; i < DIM * DIM / 4; i += 256)
        ((float4*)Ws)[i] = ((const float4*)Wg)[i];
    if (t < DIM) { as_s[t] = att_src[t]; ad_s[t] = att_dst[t]; }

    int row0 = blockIdx.x * 64;
    int nrows = min(64, NN - row0);
    for (int i = t; i < nrows * 32; i += 256) {
        int r = i >> 5, c4 = i & 31;
        ((float4*)(xs + r * DIM))[c4] = ((const float4*)(x + (size_t)(row0 + r) * DIM))[c4];
    }
    __syncthreads();

    int lane = t & 31, w = t >> 5;
    int c0 = lane * 4;
    int rbase = w * 8;
    unsigned long long acc2[8][2];
#pragma unroll
    for (int r = 0; r < 8; r++) { acc2[r][0] = 0ull; acc2[r][1] = 0ull; }

    for (int k4 = 0; k4 < DIM; k4 += 4) {
        float4 xr[8];
#pragma unroll
        for (int r = 0; r < 8; r++)
            xr[r] = *(const float4*)(xs + (rbase + r) * DIM + k4);
#pragma unroll
        for (int kk = 0; kk < 4; kk++) {
            ulonglong2 wv = *(const ulonglong2*)(Ws + (k4 + kk) * DIM + c0);
#pragma unroll
            for (int r = 0; r < 8; r++) {
                float xv = (kk == 0) ? xr[r].x : (kk == 1) ? xr[r].y : (kk == 2) ? xr[r].z : xr[r].w;
                unsigned long long xd = dup2(xv);
                acc2[r][0] = fma2(xd, wv.x, acc2[r][0]);
                acc2[r][1] = fma2(xd, wv.y, acc2[r][1]);
            }
        }
    }

    int head = c0 >> 4;        // lane/4
    int cc = c0 & 15;
#pragma unroll
    for (int r = 0; r < 8; r++) {
        int row = rbase + r;
        bool live = row < nrows;
        float2 p0 = unpk(acc2[r][0]);
        float2 p1 = unpk(acc2[r][1]);
        float a0 = p0.x, a1 = p0.y, a2 = p1.x, a3 = p1.y;
        float ss = a0 * as_s[head * HD + cc] + a1 * as_s[head * HD + cc + 1]
                 + a2 * as_s[head * HD + cc + 2] + a3 * as_s[head * HD + cc + 3];
        float sd = a0 * ad_s[head * HD + cc] + a1 * ad_s[head * HD + cc + 1]
                 + a2 * ad_s[head * HD + cc + 2] + a3 * ad_s[head * HD + cc + 3];
        ss += __shfl_xor_sync(0xffffffffu, ss, 1);
        ss += __shfl_xor_sync(0xffffffffu, ss, 2);
        sd += __shfl_xor_sync(0xffffffffu, sd, 1);
        sd += __shfl_xor_sync(0xffffffffu, sd, 2);
        if (live) {
            size_t off = (size_t)(row0 + row) * DIM + c0;
            *(float4*)(g_h + off) = make_float4(a0, a1, a2, a3);
            // self-loop contribution (alpha numerator exp(lrelu(ss+sd)))
            float wgt = expf(lrelu(ss + sd));
            *(float4*)(g_agg + off) = make_float4(a0 * wgt, a1 * wgt, a2 * wgt, a3 * wgt);
            if ((lane & 3) == 0) {
                int nh = (row0 + row) * HEADS + head;
                g_asrc[nh] = ss;
                g_adst[nh] = sd;
                g_denom[nh] = wgt;
            }
        }
    }
}

// ============================================================================
// K2: CSR aggregation — one warp per destination node. No float atomics.
// ============================================================================
__global__ void __launch_bounds__(256, 8) k_agg() {
    int d = (blockIdx.x * blockDim.x + threadIdx.x) >> 5;
    if (d >= NN) return;
    int lane = threadIdx.x & 31;
    int head = lane >> 2, c0 = lane * 4;

    float adst_h = (lane < HEADS) ? g_adst[d * HEADS + lane] : 0.f;
    int i0 = g_start[d], i1 = g_start[d + 1];
    if (i0 == i1) return;    // self-loop only; already initialized

    float accx = 0.f, accy = 0.f, accz = 0.f, accw = 0.f;
    float wsum8 = 0.f;       // per-head sum on lanes 0..7

    int s_next = __ldg(&g_csr[i0]);
    for (int i = i0; i < i1; i++) {
        int s = s_next;
        if (i + 1 < i1) s_next = __ldg(&g_csr[i + 1]);
        float w8 = 0.f;
        if (lane < HEADS)
            w8 = __expf(lrelu(__ldg(&g_asrc[s * HEADS + lane]) + adst_h));
        wsum8 += w8;
        float wgt = __shfl_sync(0xffffffffu, w8, head);
        float4 hv = __ldg((const float4*)(g_h + (size_t)s * DIM + c0));
        accx = fmaf(wgt, hv.x, accx);
        accy = fmaf(wgt, hv.y, accy);
        accz = fmaf(wgt, hv.z, accz);
        accw = fmaf(wgt, hv.w, accw);
    }

    // RMW (warp owns this node)
    float4* ap = (float4*)(g_agg + (size_t)d * DIM + c0);
    float4 cur = *ap;
    cur.x += accx; cur.y += accy; cur.z += accz; cur.w += accw;
    *ap = cur;
    if (lane < HEADS)
        g_denom[d * HEADS + lane] += wsum8;
}

// ============================================================================
// K3: fused LN1 + FFN + residual + LN2
// ============================================================================
__global__ void __launch_bounds__(256, 1)
k_ffn(const float* __restrict__ x,
      const float* __restrict__ b_gat,
      const float* __restrict__ W1,
      const float* __restrict__ b1,
      const float* __restrict__ W2,
      const float* __restrict__ b2,
      const float* __restrict__ gamma,
      const float* __restrict__ beta,
      float* __restrict__ out) {
    extern __shared__ float sm[];
    float* h1s  = sm;                        // 64*128
    float* ws1  = sm + 64 * DIM;             // 128*128
    float* ws2  = ws1 + DIM * DIM;           // 128*128
    float* mids = ws2 + DIM * DIM;           // 64*128

    int t = threadIdx.x;  // 256
    int lane = t & 31, w = t >> 5;
    int c0 = lane * 4;
    int rbase = w * 8;
    int head = c0 >> 4;
    int row0 = blockIdx.x * 64;
    int nrows = min(64, NN - row0);

    float4 gv = *(const float4*)(gamma + c0);
    float4 be = *(const float4*)(beta + c0);

    // ---- fused LN1 ----
    {
        float4 bg = *(const float4*)(b_gat + c0);
#pragma unroll
        for (int r = 0; r < 8; r++) {
            int row = rbase + r;
            if (row < nrows) {
                size_t off = (size_t)(row0 + row) * DIM + c0;
                float4 xv = *(const float4*)(x + off);
                float4 av = *(const float4*)(g_agg + off);
                float rd = 1.f / (g_denom[(row0 + row) * HEADS + head] + 1e-16f);
                float v[4] = {xv.x + av.x * rd + bg.x, xv.y + av.y * rd + bg.y,
                              xv.z + av.z * rd + bg.z, xv.w + av.w * rd + bg.w};
                float sum = v[0] + v[1] + v[2] + v[3];
#pragma unroll
                for (int o = 16; o > 0; o >>= 1) sum += __shfl_xor_sync(0xffffffffu, sum, o);
                float mu = sum * (1.f / DIM);
                float sq = 0.f;
#pragma unroll
                for (int j = 0; j < 4; j++) { float dd = v[j] - mu; sq += dd * dd; }
#pragma unroll
                for (int o = 16; o > 0; o >>= 1) sq += __shfl_xor_sync(0xffffffffu, sq, o);
                float rs = rsqrtf(sq * (1.f / DIM) + LN_EPS);
                float4 o4;
                o4.x = gv.x * (v[0] - mu) * rs + be.x;
                o4.y = gv.y * (v[1] - mu) * rs + be.y;
                o4.z = gv.z * (v[2] - mu) * rs + be.z;
                o4.w = gv.w * (v[3] - mu) * rs + be.w;
                *(float4*)(h1s + row * DIM + c0) = o4;
            } else {
                *(float4*)(h1s + row * DIM + c0) = make_float4(0.f, 0.f, 0.f, 0.f);
            }
        }
    }

    unsigned long long acc2[8][2];
#pragma unroll
    for (int r = 0; r < 8; r++) { acc2[r][0] = 0ull; acc2[r][1] = 0ull; }

    for (int kt = 0; kt < 4; kt++) {
        __syncthreads();
        for (int i = t; i < DIM * 32; i += 256) {
            int k = i >> 5, c4 = i & 31;
            ((float4*)(ws1 + k * DIM))[c4] =
                ((const float4*)(W1 + (size_t)k * 512 + kt * DIM))[c4];
        }
        for (int i = t; i < DIM * 32; i += 256)
            ((float4*)ws2)[i] = ((const float4*)(W2 + (size_t)kt * DIM * DIM))[i];
        __syncthreads();

        // ---- GEMM1 tile: mid = h1 @ W1_tile + b1_tile ----
        unsigned long long m2[8][2];
        {
            float4 b1v = *(const float4*)(b1 + kt * DIM + c0);
            unsigned long long blo, bhi;
            asm("mov.b64 %0, {%1, %2};" : "=l"(blo) : "r"(__float_as_uint(b1v.x)), "r"(__float_as_uint(b1v.y)));
            asm("mov.b64 %0, {%1, %2};" : "=l"(bhi) : "r"(__float_as_uint(b1v.z)), "r"(__float_as_uint(b1v.w)));
#pragma unroll
            for (int r = 0; r < 8; r++) { m2[r][0] = blo; m2[r][1] = bhi; }
        }
        for (int k4 = 0; k4 < DIM; k4 += 4) {
            float4 xr[8];
#pragma unroll
            for (int r = 0; r < 8; r++)
                xr[r] = *(const float4*)(h1s + (rbase + r) * DIM + k4);
#pragma unroll
            for (int kk = 0; kk < 4; kk++) {
                ulonglong2 wv = *(const ulonglong2*)(ws1 + (k4 + kk) * DIM + c0);
#pragma unroll
                for (int r = 0; r < 8; r++) {
                    float xv = (kk == 0) ? xr[r].x : (kk == 1) ? xr[r].y : (kk == 2) ? xr[r].z : xr[r].w;
                    unsigned long long xd = dup2(xv);
                    m2[r][0] = fma2(xd, wv.x, m2[r][0]);
                    m2[r][1] = fma2(xd, wv.y, m2[r][1]);
                }
            }
        }
        // exact GELU -> mids (warp-private rows)
#pragma unroll
        for (int r = 0; r < 8; r++) {
            float2 p0 = unpk(m2[r][0]);
            float2 p1 = unpk(m2[r][1]);
            float mm[4] = {p0.x, p0.y, p1.x, p1.y};
#pragma unroll
            for (int j = 0; j < 4; j++)
                mm[j] = 0.5f * mm[j] * (1.f + erff(mm[j] * 0.70710678118654752f));
            *(float4*)(mids + (rbase + r) * DIM + c0) = make_float4(mm[0], mm[1], mm[2], mm[3]);
        }
        __syncwarp();

        // ---- GEMM2 tile ----
        for (int k4 = 0; k4 < DIM; k4 += 4) {
            float4 xr[8];
#pragma unroll
            for (int r = 0; r < 8; r++)
                xr[r] = *(const float4*)(mids + (rbase + r) * DIM + k4);
#pragma unroll
            for (int kk = 0; kk < 4; kk++) {
                ulonglong2 wv = *(const ulonglong2*)(ws2 + (k4 + kk) * DIM + c0);
#pragma unroll
                for (int r = 0; r < 8; r++) {
                    float xv = (kk == 0) ? xr[r].x : (kk == 1) ? xr[r].y : (kk == 2) ? xr[r].z : xr[r].w;
                    unsigned long long xd = dup2(xv);
                    acc2[r][0] = fma2(xd, wv.x, acc2[r][0]);
                    acc2[r][1] = fma2(xd, wv.y, acc2[r][1]);
                }
            }
        }
        __syncwarp();
    }

    // ---- residual + LN2 ----
    float4 b2v = *(const float4*)(b2 + c0);
#pragma unroll
    for (int r = 0; r < 8; r++) {
        int row = rbase + r;
        if (row >= nrows) continue;
        float2 p0 = unpk(acc2[r][0]);
        float2 p1 = unpk(acc2[r][1]);
        float v[4];
        v[0] = p0.x + b2v.x + h1s[row * DIM + c0 + 0];
        v[1] = p0.y + b2v.y + h1s[row * DIM + c0 + 1];
        v[2] = p1.x + b2v.z + h1s[row * DIM + c0 + 2];
        v[3] = p1.y + b2v.w + h1s[row * DIM + c0 + 3];
        float sum = v[0] + v[1] + v[2] + v[3];
#pragma unroll
        for (int o = 16; o > 0; o >>= 1) sum += __shfl_xor_sync(0xffffffffu, sum, o);
        float mu = sum * (1.f / DIM);
        float sq = 0.f;
#pragma unroll
        for (int j = 0; j < 4; j++) { float dd = v[j] - mu; sq += dd * dd; }
#pragma unroll
        for (int o = 16; o > 0; o >>= 1) sq += __shfl_xor_sync(0xffffffffu, sq, o);
        float rs = rsqrtf(sq * (1.f / DIM) + LN_EPS);
        float4 o4;
        o4.x = gv.x * (v[0] - mu) * rs + be.x;
        o4.y = gv.y * (v[1] - mu) * rs + be.y;
        o4.z = gv.z * (v[2] - mu) * rs + be.z;
        o4.w = gv.w * (v[3] - mu) * rs + be.w;
        *(float4*)(out + (size_t)(row0 + row) * DIM + c0) = o4;
    }
}

// ============================================================================
extern "C" void kernel_launch(void* const* d_in, const int* in_sizes, int n_in,
                              void* d_out, int out_size) {
    const float* x        = (const float*)d_in[0];
    const void*  ei       = d_in[1];
    const float* W_gat    = (const float*)d_in[2];
    const float* att_src  = (const float*)d_in[3];
    const float* att_dst  = (const float*)d_in[4];
    const float* b_gat    = (const float*)d_in[5];
    const float* gamma    = (const float*)d_in[6];
    const float* beta     = (const float*)d_in[7];
    const float* W1       = (const float*)d_in[8];
    const float* b1       = (const float*)d_in[9];
    const float* W2       = (const float*)d_in[10];
    const float* b2       = (const float*)d_in[11];
    float* out = (float*)d_out;

    const int smem_gat = (DIM * DIM + 64 * DIM) * sizeof(float);                 // 96 KB
    const int smem_ffn = (64 * DIM + 2 * DIM * DIM + 64 * DIM) * sizeof(float);  // 192 KB
    cudaFuncSetAttribute(k_gat_gemm, cudaFuncAttributeMaxDynamicSharedMemorySize, smem_gat);
    cudaFuncSetAttribute(k_ffn, cudaFuncAttributeMaxDynamicSharedMemorySize, smem_ffn);

    const int rowBlocks = (NN + 63) / 64;   // 1563

    k_detect<<<1, 1>>>((const unsigned*)ei);
    k_convert<<<(2 * EE + 255) / 256, 256>>>(ei);
    k_hist<<<(EE + 255) / 256, 256>>>();
    k_scan<<<1, 1024>>>();
    k_scatter<<<(EE + 255) / 256, 256>>>();
    k_gat_gemm<<<rowBlocks, 256, smem_gat>>>(x, W_gat, att_src, att_dst);
    k_agg<<<(NN * 32 + 255) / 256, 256>>>();
    k_ffn<<<rowBlocks, 256, smem_ffn>>>(x, b_gat, W1, b1, W2, b2, gamma, beta, out);
}

// round 7
// speedup vs baseline: 1.5141x; 1.0678x over previous
#include <cuda_runtime.h>
#include <cuda_bf16.h>
#include <math.h>

#define NN 100000
#define DIM 128
#define HEADS 8
#define HD 16
#define EE 1600000
#define SLOPE 0.2f
#define LN_EPS 1e-5f
#define SCAN_B 98            // ceil(NN / 1024)

// ---------------- scratch (device globals; no allocation allowed) ----------------
__device__ float g_h[(size_t)NN * DIM];       // x @ W_gat
__device__ float g_asrc[NN * HEADS];
__device__ float g_adst[NN * HEADS];
__device__ float g_denom[NN * HEADS];         // sum of exp(e) per (node, head)
__device__ float g_agg[(size_t)NN * DIM];     // UNnormalized aggregated messages
__device__ int g_deg[NN];
__device__ int g_start[NN + 1];
__device__ int g_cursor[NN];
__device__ int g_csr[EE];                      // src ids grouped by dst
__device__ int g_btot[SCAN_B];
__device__ int g_boff[SCAN_B];
__device__ int g_is64;

// ---------------- helpers ----------------
__device__ __forceinline__ float lrelu(float x) { return x > 0.f ? x : SLOPE * x; }

// packed f32x2 helpers (sm_103a)
__device__ __forceinline__ unsigned long long dup2(float x) {
    unsigned long long r; unsigned u = __float_as_uint(x);
    asm("mov.b64 %0, {%1, %2};" : "=l"(r) : "r"(u), "r"(u));
    return r;
}
__device__ __forceinline__ unsigned long long fma2(unsigned long long a, unsigned long long b, unsigned long long c) {
    unsigned long long d;
    asm("fma.rn.f32x2 %0, %1, %2, %3;" : "=l"(d) : "l"(a), "l"(b), "l"(c));
    return d;
}
__device__ __forceinline__ float2 unpk(unsigned long long v) {
    unsigned lo, hi;
    asm("mov.b64 {%0, %1}, %2;" : "=r"(lo), "=r"(hi) : "l"(v));
    return make_float2(__uint_as_float(lo), __uint_as_float(hi));
}

__device__ __forceinline__ int edge_val(const void* ei, int is64, size_t idx) {
    return is64 ? (int)((const long long*)ei)[idx] : ((const int*)ei)[idx];
}

// ============================================================================
// K0a: sniff edge_index dtype. int64 values < 2^31 -> every odd 32-bit word 0.
// ============================================================================
__global__ void k_detect(const unsigned* __restrict__ w) {
    unsigned nz = 0;
    for (int i = 1; i < 256; i += 2) nz |= w[i];
    g_is64 = (nz == 0) ? 1 : 0;
}

// K0b: zero degree histogram
__global__ void k_zero() {
    int i = blockIdx.x * blockDim.x + threadIdx.x;
    if (i < NN) g_deg[i] = 0;
}

// K0c: degree histogram over destinations (reads raw edge_index)
__global__ void k_hist(const void* __restrict__ ei) {
    int i = blockIdx.x * blockDim.x + threadIdx.x;
    if (i >= EE) return;
    int is64 = g_is64;
    int d = edge_val(ei, is64, (size_t)EE + i);
    atomicAdd(&g_deg[d], 1);
}

// K0d-1: per-block local exclusive scan + block totals
__global__ void __launch_bounds__(1024, 1) k_scan1() {
    __shared__ int warp_tot[32];
    int t = threadIdx.x, lane = t & 31, wid = t >> 5;
    int i = blockIdx.x * 1024 + t;
    int v = (i < NN) ? g_deg[i] : 0;
    int incl = v;
#pragma unroll
    for (int o = 1; o < 32; o <<= 1) {
        int n = __shfl_up_sync(0xffffffffu, incl, o);
        if (lane >= o) incl += n;
    }
    if (lane == 31) warp_tot[wid] = incl;
    __syncthreads();
    if (wid == 0) {
        int wv = warp_tot[lane];
        int wincl = wv;
#pragma unroll
        for (int o = 1; o < 32; o <<= 1) {
            int n = __shfl_up_sync(0xffffffffu, wincl, o);
            if (lane >= o) wincl += n;
        }
        warp_tot[lane] = wincl - wv;   // exclusive warp offsets
    }
    __syncthreads();
    int excl = warp_tot[wid] + (incl - v);
    if (i < NN) g_start[i] = excl;     // local (block-relative) for now
    if (t == 1023) g_btot[blockIdx.x] = excl + v;
}

// K0d-2: single block scans the 98 block totals -> exclusive offsets
__global__ void k_scan2() {
    int t = threadIdx.x;               // 128 threads
    __shared__ int wt[4];
    int lane = t & 31, wid = t >> 5;
    int v = (t < SCAN_B) ? g_btot[t] : 0;
    int incl = v;
#pragma unroll
    for (int o = 1; o < 32; o <<= 1) {
        int n = __shfl_up_sync(0xffffffffu, incl, o);
        if (lane >= o) incl += n;
    }
    if (lane == 31) wt[wid] = incl;
    __syncthreads();
    int off = 0;
    for (int ww = 0; ww < wid; ww++) off += wt[ww];
    if (t < SCAN_B) g_boff[t] = off + incl - v;
}

// K0d-3: add block offsets; init cursor
__global__ void __launch_bounds__(1024, 1) k_scan3() {
    int i = blockIdx.x * 1024 + threadIdx.x;
    if (i < NN) {
        int v = g_start[i] + g_boff[blockIdx.x];
        g_start[i] = v;
        g_cursor[i] = v;
    }
    if (i == 0) g_start[NN] = EE;
}

// K0e: scatter src ids into dst buckets (reads raw edge_index)
__global__ void k_scatter(const void* __restrict__ ei) {
    int i = blockIdx.x * blockDim.x + threadIdx.x;
    if (i >= EE) return;
    int is64 = g_is64;
    int s = edge_val(ei, is64, i);
    int d = edge_val(ei, is64, (size_t)EE + i);
    int pos = atomicAdd(&g_cursor[d], 1);
    g_csr[pos] = s;
}

// ============================================================================
// K1: h = x @ W_gat (packed f32x2 FMA), attention dots, AND self-loop init of
//     g_agg / g_denom (acc values still in registers).
// ============================================================================
__global__ void __launch_bounds__(256, 1)
k_gat_gemm(const float* __restrict__ x,
           const float* __restrict__ Wg,
           const float* __restrict__ att_src,
           const float* __restrict__ att_dst) {
    extern __shared__ float sm[];
    float* Ws = sm;                 // 128*128
    float* xs = sm + DIM * DIM;     // 64*128
    __shared__ float as_s[DIM], ad_s[DIM];

    int t = threadIdx.x;            // 256 threads
    for (int i = t; i < DIM * DIM / 4; i += 256)
        ((float4*)Ws)[i] = ((const float4*)Wg)[i];
    if (t < DIM) { as_s[t] = att_src[t]; ad_s[t] = att_dst[t]; }

    int row0 = blockIdx.x * 64;
    int nrows = min(64, NN - row0);
    for (int i = t; i < nrows * 32; i += 256) {
        int r = i >> 5, c4 = i & 31;
        ((float4*)(xs + r * DIM))[c4] = ((const float4*)(x + (size_t)(row0 + r) * DIM))[c4];
    }
    __syncthreads();

    int lane = t & 31, w = t >> 5;
    int c0 = lane * 4;
    int rbase = w * 8;
    unsigned long long acc2[8][2];
#pragma unroll
    for (int r = 0; r < 8; r++) { acc2[r][0] = 0ull; acc2[r][1] = 0ull; }

    for (int k4 = 0; k4 < DIM; k4 += 4) {
        float4 xr[8];
#pragma unroll
        for (int r = 0; r < 8; r++)
            xr[r] = *(const float4*)(xs + (rbase + r) * DIM + k4);
#pragma unroll
        for (int kk = 0; kk < 4; kk++) {
            ulonglong2 wv = *(const ulonglong2*)(Ws + (k4 + kk) * DIM + c0);
#pragma unroll
            for (int r = 0; r < 8; r++) {
                float xv = (kk == 0) ? xr[r].x : (kk == 1) ? xr[r].y : (kk == 2) ? xr[r].z : xr[r].w;
                unsigned long long xd = dup2(xv);
                acc2[r][0] = fma2(xd, wv.x, acc2[r][0]);
                acc2[r][1] = fma2(xd, wv.y, acc2[r][1]);
            }
        }
    }

    int head = c0 >> 4;        // lane/4
    int cc = c0 & 15;
#pragma unroll
    for (int r = 0; r < 8; r++) {
        int row = rbase + r;
        bool live = row < nrows;
        float2 p0 = unpk(acc2[r][0]);
        float2 p1 = unpk(acc2[r][1]);
        float a0 = p0.x, a1 = p0.y, a2 = p1.x, a3 = p1.y;
        float ss = a0 * as_s[head * HD + cc] + a1 * as_s[head * HD + cc + 1]
                 + a2 * as_s[head * HD + cc + 2] + a3 * as_s[head * HD + cc + 3];
        float sd = a0 * ad_s[head * HD + cc] + a1 * ad_s[head * HD + cc + 1]
                 + a2 * ad_s[head * HD + cc + 2] + a3 * ad_s[head * HD + cc + 3];
        ss += __shfl_xor_sync(0xffffffffu, ss, 1);
        ss += __shfl_xor_sync(0xffffffffu, ss, 2);
        sd += __shfl_xor_sync(0xffffffffu, sd, 1);
        sd += __shfl_xor_sync(0xffffffffu, sd, 2);
        if (live) {
            size_t off = (size_t)(row0 + row) * DIM + c0;
            *(float4*)(g_h + off) = make_float4(a0, a1, a2, a3);
            // self-loop contribution (alpha numerator exp(lrelu(ss+sd)))
            float wgt = expf(lrelu(ss + sd));
            *(float4*)(g_agg + off) = make_float4(a0 * wgt, a1 * wgt, a2 * wgt, a3 * wgt);
            if ((lane & 3) == 0) {
                int nh = (row0 + row) * HEADS + head;
                g_asrc[nh] = ss;
                g_adst[nh] = sd;
                g_denom[nh] = wgt;
            }
        }
    }
}

// ============================================================================
// K2: CSR aggregation — one warp per destination node, 4 edges per iteration.
//     All lanes compute weights (4 edges x 8 heads); 4 independent row gathers.
// ============================================================================
__global__ void __launch_bounds__(256, 8) k_agg() {
    int d = (blockIdx.x * blockDim.x + threadIdx.x) >> 5;
    if (d >= NN) return;
    int lane = threadIdx.x & 31;
    int head4 = lane >> 2;           // head owning this lane's 4 channels
    int h8 = lane & 7;               // head used in weight computation
    int egrp = lane >> 3;            // edge slot 0..3
    int c0 = lane * 4;

    int i0 = g_start[d], i1 = g_start[d + 1];
    if (i0 == i1) return;            // self-loop only; already initialized

    float adst_l = __ldg(&g_adst[d * HEADS + h8]);

    float accx = 0.f, accy = 0.f, accz = 0.f, accw = 0.f;
    float wsum = 0.f;

    for (int i = i0; i < i1; i += 4) {
        int idx = i + egrp;
        int sA = 0; float w = 0.f;
        if (idx < i1) {
            sA = __ldg(&g_csr[idx]);
            w = __expf(lrelu(__ldg(&g_asrc[sA * HEADS + h8]) + adst_l));
        }
        wsum += w;
        int rem = i1 - i;            // uniform across warp
#pragma unroll
        for (int e = 0; e < 4; e++) {
            if (e >= rem) break;
            int s = __shfl_sync(0xffffffffu, sA, e * 8);
            float wgt = __shfl_sync(0xffffffffu, w, e * 8 + head4);
            float4 hv = __ldg((const float4*)(g_h + (size_t)s * DIM + c0));
            accx = fmaf(wgt, hv.x, accx);
            accy = fmaf(wgt, hv.y, accy);
            accz = fmaf(wgt, hv.z, accz);
            accw = fmaf(wgt, hv.w, accw);
        }
    }

    // per-head weight sums: combine the 4 edge groups (lanes h, h+8, h+16, h+24)
    wsum += __shfl_xor_sync(0xffffffffu, wsum, 8);
    wsum += __shfl_xor_sync(0xffffffffu, wsum, 16);

    // RMW (warp owns this node)
    float4* ap = (float4*)(g_agg + (size_t)d * DIM + c0);
    float4 cur = *ap;
    cur.x += accx; cur.y += accy; cur.z += accz; cur.w += accw;
    *ap = cur;
    if (lane < HEADS)
        g_denom[d * HEADS + lane] += wsum;
}

// ============================================================================
// K3: fused LN1 + FFN + residual + LN2
// ============================================================================
__global__ void __launch_bounds__(256, 1)
k_ffn(const float* __restrict__ x,
      const float* __restrict__ b_gat,
      const float* __restrict__ W1,
      const float* __restrict__ b1,
      const float* __restrict__ W2,
      const float* __restrict__ b2,
      const float* __restrict__ gamma,
      const float* __restrict__ beta,
      float* __restrict__ out) {
    extern __shared__ float sm[];
    float* h1s  = sm;                        // 64*128
    float* ws1  = sm + 64 * DIM;             // 128*128
    float* ws2  = ws1 + DIM * DIM;           // 128*128
    float* mids = ws2 + DIM * DIM;           // 64*128

    int t = threadIdx.x;  // 256
    int lane = t & 31, w = t >> 5;
    int c0 = lane * 4;
    int rbase = w * 8;
    int head = c0 >> 4;
    int row0 = blockIdx.x * 64;
    int nrows = min(64, NN - row0);

    float4 gv = *(const float4*)(gamma + c0);
    float4 be = *(const float4*)(beta + c0);

    // ---- fused LN1 ----
    {
        float4 bg = *(const float4*)(b_gat + c0);
#pragma unroll
        for (int r = 0; r < 8; r++) {
            int row = rbase + r;
            if (row < nrows) {
                size_t off = (size_t)(row0 + row) * DIM + c0;
                float4 xv = *(const float4*)(x + off);
                float4 av = *(const float4*)(g_agg + off);
                float rd = 1.f / (g_denom[(row0 + row) * HEADS + head] + 1e-16f);
                float v[4] = {xv.x + av.x * rd + bg.x, xv.y + av.y * rd + bg.y,
                              xv.z + av.z * rd + bg.z, xv.w + av.w * rd + bg.w};
                float sum = v[0] + v[1] + v[2] + v[3];
#pragma unroll
                for (int o = 16; o > 0; o >>= 1) sum += __shfl_xor_sync(0xffffffffu, sum, o);
                float mu = sum * (1.f / DIM);
                float sq = 0.f;
#pragma unroll
                for (int j = 0; j < 4; j++) { float dd = v[j] - mu; sq += dd * dd; }
#pragma unroll
                for (int o = 16; o > 0; o >>= 1) sq += __shfl_xor_sync(0xffffffffu, sq, o);
                float rs = rsqrtf(sq * (1.f / DIM) + LN_EPS);
                float4 o4;
                o4.x = gv.x * (v[0] - mu) * rs + be.x;
                o4.y = gv.y * (v[1] - mu) * rs + be.y;
                o4.z = gv.z * (v[2] - mu) * rs + be.z;
                o4.w = gv.w * (v[3] - mu) * rs + be.w;
                *(float4*)(h1s + row * DIM + c0) = o4;
            } else {
                *(float4*)(h1s + row * DIM + c0) = make_float4(0.f, 0.f, 0.f, 0.f);
            }
        }
    }

    unsigned long long acc2[8][2];
#pragma unroll
    for (int r = 0; r < 8; r++) { acc2[r][0] = 0ull; acc2[r][1] = 0ull; }

    for (int kt = 0; kt < 4; kt++) {
        __syncthreads();
        for (int i = t; i < DIM * 32; i += 256) {
            int k = i >> 5, c4 = i & 31;
            ((float4*)(ws1 + k * DIM))[c4] =
                ((const float4*)(W1 + (size_t)k * 512 + kt * DIM))[c4];
        }
        for (int i = t; i < DIM * 32; i += 256)
            ((float4*)ws2)[i] = ((const float4*)(W2 + (size_t)kt * DIM * DIM))[i];
        __syncthreads();

        // ---- GEMM1 tile: mid = h1 @ W1_tile + b1_tile ----
        unsigned long long m2[8][2];
        {
            float4 b1v = *(const float4*)(b1 + kt * DIM + c0);
            unsigned long long blo, bhi;
            asm("mov.b64 %0, {%1, %2};" : "=l"(blo) : "r"(__float_as_uint(b1v.x)), "r"(__float_as_uint(b1v.y)));
            asm("mov.b64 %0, {%1, %2};" : "=l"(bhi) : "r"(__float_as_uint(b1v.z)), "r"(__float_as_uint(b1v.w)));
#pragma unroll
            for (int r = 0; r < 8; r++) { m2[r][0] = blo; m2[r][1] = bhi; }
        }
        for (int k4 = 0; k4 < DIM; k4 += 4) {
            float4 xr[8];
#pragma unroll
            for (int r = 0; r < 8; r++)
                xr[r] = *(const float4*)(h1s + (rbase + r) * DIM + k4);
#pragma unroll
            for (int kk = 0; kk < 4; kk++) {
                ulonglong2 wv = *(const ulonglong2*)(ws1 + (k4 + kk) * DIM + c0);
#pragma unroll
                for (int r = 0; r < 8; r++) {
                    float xv = (kk == 0) ? xr[r].x : (kk == 1) ? xr[r].y : (kk == 2) ? xr[r].z : xr[r].w;
                    unsigned long long xd = dup2(xv);
                    m2[r][0] = fma2(xd, wv.x, m2[r][0]);
                    m2[r][1] = fma2(xd, wv.y, m2[r][1]);
                }
            }
        }
        // exact GELU -> mids (warp-private rows)
#pragma unroll
        for (int r = 0; r < 8; r++) {
            float2 p0 = unpk(m2[r][0]);
            float2 p1 = unpk(m2[r][1]);
            float mm[4] = {p0.x, p0.y, p1.x, p1.y};
#pragma unroll
            for (int j = 0; j < 4; j++)
                mm[j] = 0.5f * mm[j] * (1.f + erff(mm[j] * 0.70710678118654752f));
            *(float4*)(mids + (rbase + r) * DIM + c0) = make_float4(mm[0], mm[1], mm[2], mm[3]);
        }
        __syncwarp();

        // ---- GEMM2 tile ----
        for (int k4 = 0; k4 < DIM; k4 += 4) {
            float4 xr[8];
#pragma unroll
            for (int r = 0; r < 8; r++)
                xr[r] = *(const float4*)(mids + (rbase + r) * DIM + k4);
#pragma unroll
            for (int kk = 0; kk < 4; kk++) {
                ulonglong2 wv = *(const ulonglong2*)(ws2 + (k4 + kk) * DIM + c0);
#pragma unroll
                for (int r = 0; r < 8; r++) {
                    float xv = (kk == 0) ? xr[r].x : (kk == 1) ? xr[r].y : (kk == 2) ? xr[r].z : xr[r].w;
                    unsigned long long xd = dup2(xv);
                    acc2[r][0] = fma2(xd, wv.x, acc2[r][0]);
                    acc2[r][1] = fma2(xd, wv.y, acc2[r][1]);
                }
            }
        }
        __syncwarp();
    }

    // ---- residual + LN2 ----
    float4 b2v = *(const float4*)(b2 + c0);
#pragma unroll
    for (int r = 0; r < 8; r++) {
        int row = rbase + r;
        if (row >= nrows) continue;
        float2 p0 = unpk(acc2[r][0]);
        float2 p1 = unpk(acc2[r][1]);
        float v[4];
        v[0] = p0.x + b2v.x + h1s[row * DIM + c0 + 0];
        v[1] = p0.y + b2v.y + h1s[row * DIM + c0 + 1];
        v[2] = p1.x + b2v.z + h1s[row * DIM + c0 + 2];
        v[3] = p1.y + b2v.w + h1s[row * DIM + c0 + 3];
        float sum = v[0] + v[1] + v[2] + v[3];
#pragma unroll
        for (int o = 16; o > 0; o >>= 1) sum += __shfl_xor_sync(0xffffffffu, sum, o);
        float mu = sum * (1.f / DIM);
        float sq = 0.f;
#pragma unroll
        for (int j = 0; j < 4; j++) { float dd = v[j] - mu; sq += dd * dd; }
#pragma unroll
        for (int o = 16; o > 0; o >>= 1) sq += __shfl_xor_sync(0xffffffffu, sq, o);
        float rs = rsqrtf(sq * (1.f / DIM) + LN_EPS);
        float4 o4;
        o4.x = gv.x * (v[0] - mu) * rs + be.x;
        o4.y = gv.y * (v[1] - mu) * rs + be.y;
        o4.z = gv.z * (v[2] - mu) * rs + be.z;
        o4.w = gv.w * (v[3] - mu) * rs + be.w;
        *(float4*)(out + (size_t)(row0 + row) * DIM + c0) = o4;
    }
}

// ============================================================================
extern "C" void kernel_launch(void* const* d_in, const int* in_sizes, int n_in,
                              void* d_out, int out_size) {
    const float* x        = (const float*)d_in[0];
    const void*  ei       = d_in[1];
    const float* W_gat    = (const float*)d_in[2];
    const float* att_src  = (const float*)d_in[3];
    const float* att_dst  = (const float*)d_in[4];
    const float* b_gat    = (const float*)d_in[5];
    const float* gamma    = (const float*)d_in[6];
    const float* beta     = (const float*)d_in[7];
    const float* W1       = (const float*)d_in[8];
    const float* b1       = (const float*)d_in[9];
    const float* W2       = (const float*)d_in[10];
    const float* b2       = (const float*)d_in[11];
    float* out = (float*)d_out;

    const int smem_gat = (DIM * DIM + 64 * DIM) * sizeof(float);                 // 96 KB
    const int smem_ffn = (64 * DIM + 2 * DIM * DIM + 64 * DIM) * sizeof(float);  // 192 KB
    cudaFuncSetAttribute(k_gat_gemm, cudaFuncAttributeMaxDynamicSharedMemorySize, smem_gat);
    cudaFuncSetAttribute(k_ffn, cudaFuncAttributeMaxDynamicSharedMemorySize, smem_ffn);

    const int rowBlocks = (NN + 63) / 64;   // 1563

    k_detect<<<1, 1>>>((const unsigned*)ei);
    k_zero<<<SCAN_B, 1024>>>();
    k_hist<<<(EE + 255) / 256, 256>>>(ei);
    k_scan1<<<SCAN_B, 1024>>>();
    k_scan2<<<1, 128>>>();
    k_scan3<<<SCAN_B, 1024>>>();
    k_scatter<<<(EE + 255) / 256, 256>>>(ei);
    k_gat_gemm<<<rowBlocks, 256, smem_gat>>>(x, W_gat, att_src, att_dst);
    k_agg<<<(NN * 32 + 255) / 256, 256>>>();
    k_ffn<<<rowBlocks, 256, smem_ffn>>>(x, b_gat, W1, b1, W2, b2, gamma, beta, out);
}